// round 16
// baseline (speedup 1.0000x reference)
#include <cuda_runtime.h>

// EnhancedLesionPenaltyLoss: pred (16,1,128,128,128) fp32 -> scalar loss.
// R15 memory structure (v8 loads + distance-2 rotating prefetch, h JIT) with:
//  (1) fine-grain blocks: 1024 x 128thr -> 6.92 blocks/SM vs cap 8 => ~1%
//      SM load imbalance (512x256 had ~13%);
//  (2) split accumulator chains: gw/gh/gd separate, tree-summed diffs,
//      s1/s2/ci/mx split even/odd -> chain latency per iter ~3x shorter.
// Grid: 16 batches x 16 strips(8 rows) x 4 zsegs(32 planes) = 1024 blocks.
// Integer threshold compares + packed counters + integer max.
// Last block (atomic ticket) does the deterministic final reduction.

namespace {
constexpr int NB      = 16;
constexpr int STRIPS  = 16;
constexpr int ZSEGS   = 4;
constexpr int ZLEN    = 32;
constexpr int NBLK    = NB * STRIPS * ZSEGS;   // 1024
constexpr int THREADS = 128;
constexpr int NACC    = 6;               // cmin,cmax,max,sds,s1,s2
constexpr unsigned U01 = 0x3C23D70Au;    // bits of 0.01f
constexpr unsigned U05 = 0x3F000000u;    // bits of 0.5f
}

__device__ float        g_part[NBLK * NACC];
__device__ unsigned int g_ticket = 0;

__device__ __forceinline__ void ldg256(float v[8], const char* p) {
    asm("ld.global.v8.f32 {%0,%1,%2,%3,%4,%5,%6,%7}, [%8];"
        : "=f"(v[0]), "=f"(v[1]), "=f"(v[2]), "=f"(v[3]),
          "=f"(v[4]), "=f"(v[5]), "=f"(v[6]), "=f"(v[7])
        : "l"(p));
}

struct St {
    unsigned ciA, ciB;      // packed ci|ch<<16, even/odd split
    unsigned mxA, mxB;      // integer max split
    float gw, gh, gd;       // gradient sums split by direction
    float s1A, s1B, s2A, s2B;
};

__device__ __forceinline__ void body(const float v[8], const float prev[8],
                                     const char* pz,
                                     bool do_h, bool do_w, St& st) {
    // w-direction: own chain.
    const float nx = __shfl_down_sync(0xffffffffu, v[0], 1);
    {
        float a = (fabsf(v[1] - v[0]) + fabsf(v[2] - v[1])) +
                  (fabsf(v[3] - v[2]) + fabsf(v[4] - v[3]));
        float c = (fabsf(v[5] - v[4]) + fabsf(v[6] - v[5])) +
                   fabsf(v[7] - v[6]);
        if (do_w) c += fabsf(nx - v[7]);
        st.gw += a + c;
    }
    // h-direction: JIT load (L1-hit; line prefetched as v by row+1 thread),
    // tree-summed, own chain.
    if (do_h) {
        float h[8];
        ldg256(h, pz + 512);
        const float t = ((fabsf(h[0] - v[0]) + fabsf(h[1] - v[1])) +
                         (fabsf(h[2] - v[2]) + fabsf(h[3] - v[3]))) +
                        ((fabsf(h[4] - v[4]) + fabsf(h[5] - v[5])) +
                         (fabsf(h[6] - v[6]) + fabsf(h[7] - v[7])));
        st.gh += t;
    }
    // d-direction: prev plane in registers, tree-summed, own chain.
    {
        const float t = ((fabsf(v[0] - prev[0]) + fabsf(v[1] - prev[1])) +
                         (fabsf(v[2] - prev[2]) + fabsf(v[3] - prev[3]))) +
                        ((fabsf(v[4] - prev[4]) + fabsf(v[5] - prev[5])) +
                         (fabsf(v[6] - prev[6]) + fabsf(v[7] - prev[7])));
        st.gd += t;
    }
    // thresholds: even/odd split chains.
#pragma unroll
    for (int k = 0; k < 8; k += 2) {
        const float    xa  = v[k],     xb  = v[k + 1];
        const unsigned ua  = __float_as_uint(xa);
        const unsigned ub  = __float_as_uint(xb);
        if (ua > U01) { st.ciA += 1u; st.s1A += xa; st.s2A = fmaf(xa, xa, st.s2A); }
        if (ub > U01) { st.ciB += 1u; st.s1B += xb; st.s2B = fmaf(xb, xb, st.s2B); }
        if (ua > U05) st.ciA += 0x10000u;
        if (ub > U05) st.ciB += 0x10000u;
        st.mxA = (ua > st.mxA) ? ua : st.mxA;
        st.mxB = (ub > st.mxB) ? ub : st.mxB;
    }
}

__global__ __launch_bounds__(THREADS, 8)
void lesion_fused(const float* __restrict__ pred, float* __restrict__ out) {
    const int bid   = blockIdx.x;
    const int zseg  = bid & 3;
    const int strip = (bid >> 2) & 15;
    const int b     = bid >> 6;
    const int tid   = threadIdx.x;
    const int lane  = tid & 31;
    const int wid   = tid >> 5;

    const int col8 = tid & 15;             // 8-float column group (0..15)
    const int rloc = tid >> 4;             // row within strip (0..7)
    const int grow = strip * 8 + rloc;     // global row (0..127)
    const bool do_h = (grow < 127);
    const bool do_w = (col8 != 15);
    const int  z0   = zseg * ZLEN;

    const char* pv = reinterpret_cast<const char*>(pred) +
                     (size_t)b * 8388608 + (size_t)z0 * 65536 +
                     (size_t)grow * 512 + (size_t)col8 * 32;

    St st = {0u,0u, 0u,0u, 0.f,0.f,0.f, 0.f,0.f,0.f,0.f};

    float V[4][8];
    // Seed: V[3] = prev plane (z0-1; z0==0 -> plane 0, self-diff = 0).
    ldg256(V[3], (z0 > 0) ? (pv - 65536) : pv);
    ldg256(V[0], pv);                       // plane 0
    ldg256(V[1], pv + 65536);               // plane 1

    for (int i0 = 0; i0 < ZLEN; i0 += 4) {
#pragma unroll
        for (int k = 0; k < 4; ++k) {
            const int i  = i0 + k;
            // distance-2 prefetch into the free ring slot.
            const int zn = (i + 2 < ZLEN) ? (i + 2) : (ZLEN - 1);
            ldg256(V[(k + 2) & 3], pv + (size_t)zn * 65536);

            body(V[k & 3], V[(k + 3) & 3], pv + (size_t)i * 65536,
                 do_h, do_w, st);
        }
    }

    // merge split chains (fixed order -> deterministic)
    const unsigned cic = st.ciA + st.ciB;
    const unsigned mxu = (st.mxA > st.mxB) ? st.mxA : st.mxB;
    const float sds = st.gw + st.gh + st.gd;
    const float s1  = st.s1A + st.s1B;
    const float s2  = st.s2A + st.s2B;

    // ---- block reduction (4 warps) ----
    float acc[NACC] = {(float)(cic & 0xFFFFu), (float)(cic >> 16),
                       __uint_as_float(mxu), sds, s1, s2};
#pragma unroll
    for (int k = 0; k < NACC; ++k) {
#pragma unroll
        for (int off = 16; off; off >>= 1) {
            const float t = __shfl_xor_sync(0xffffffffu, acc[k], off);
            acc[k] = (k == 2) ? fmaxf(acc[k], t) : (acc[k] + t);
        }
    }
    __shared__ float red[4][NACC];
    __shared__ float fin[NB][NACC];
    __shared__ float lsh[NB];
    __shared__ unsigned int tick_sh;
    if (lane == 0) {
#pragma unroll
        for (int k = 0; k < NACC; ++k) red[wid][k] = acc[k];
    }
    __syncthreads();

    if (tid == 0) {
#pragma unroll
        for (int k = 0; k < NACC; ++k) {
            float r = red[0][k];
#pragma unroll
            for (int w = 1; w < 4; ++w)
                r = (k == 2) ? fmaxf(r, red[w][k]) : (r + red[w][k]);
            g_part[bid * NACC + k] = r;
        }
        __threadfence();
        tick_sh = atomicAdd(&g_ticket, 1u);
    }
    __syncthreads();
    if (tick_sh != (unsigned)(NBLK - 1)) return;

    // ---- last block: deterministic fixed-order final reduction ----
    __threadfence();  // acquire other blocks' g_part writes

    constexpr int PER_B = STRIPS * ZSEGS;  // 64 partials per batch
    if (tid < NB * NACC) {
        const int fb = tid / NACC;
        const int fk = tid % NACC;
        const float* base = &g_part[(fb * PER_B) * NACC + fk];
        float r = base[0];
#pragma unroll
        for (int c2 = 1; c2 < PER_B; ++c2) {
            const float t = base[c2 * NACC];
            r = (fk == 2) ? fmaxf(r, t) : (r + t);
        }
        fin[fb][fk] = r;
    }
    __syncthreads();

    if (tid < NB) {
        const float cnt   = fin[tid][0];
        const float chigh = fin[tid][1];
        const float mxv   = fin[tid][2];
        const float sg    = fin[tid][3];
        const float S1    = fin[tid][4];
        const float S2    = fin[tid][5];

        const float invN   = 1.f / 2097152.f;        // 1/128^3
        const float invND3 = 1.f / 6242304.f;        // 1/(3*127*128*128)

        const float act = cnt * invN;
        float loss = fmaxf(0.005f - act, 0.f) * 15.f;

        const float high = chigh * invN;
        loss += fmaxf(high - 0.03f, 0.f) * 5.f;

        const float avg_grad = sg * invND3;
        if (mxv > 0.3f) loss += fminf(avg_grad, 1.f) * 5.f;

        const float cnt_safe = fmaxf(cnt, 1.f);
        const float m  = S1 / cnt_safe;
        const float sq = fmaxf(S2 - 2.f * m * S1 + m * m * cnt, 0.f);
        const bool gate = (act > 0.001f) && (cnt > 1.f);
        const float var = gate ? (sq / fmaxf(cnt - 1.f, 1.f)) : 1.f;
        const float rel_std = sqrtf(var) / (m + 1e-6f);
        const float pen = expf(-5.f * rel_std);
        loss += (gate ? pen : 0.f) * 7.f;

        lsh[tid] = loss;
    }
    __syncthreads();
    if (tid == 0) {
        float t = 0.f;
#pragma unroll
        for (int i = 0; i < NB; ++i) t += lsh[i];
        out[0] = t * (1.f / 16.f);
        g_ticket = 0;  // reset for next (graph-replayed) launch
    }
}

extern "C" void kernel_launch(void* const* d_in, const int* in_sizes, int n_in,
                              void* d_out, int out_size) {
    (void)in_sizes; (void)n_in; (void)out_size;
    const float* pred = (const float*)d_in[0];
    float* out = (float*)d_out;
    lesion_fused<<<NBLK, THREADS>>>(pred, out);
}

// round 17
// speedup vs baseline: 1.0010x; 1.0010x over previous
#include <cuda_runtime.h>

// EnhancedLesionPenaltyLoss: pred (16,1,128,128,128) fp32 -> scalar loss.
// R15 structure (v8 loads + distance-2 rotating register prefetch, h JIT)
// with finer z-granularity for SM drain-balance: ZSEGS=8 (16 planes/block)
// -> 1024 blocks at occupancy 4/SM drain with ~4% tail (512 blocks had
// 15.6% wave imbalance at 3.46 blocks/SM).
// Grid: 16 batches x 8 strips(16 rows) x 8 zsegs(16 planes) = 1024 x 256.
// Integer threshold compares + packed counters + integer max.
// Last block (atomic ticket) does the deterministic final reduction.

namespace {
constexpr int NB      = 16;
constexpr int STRIPS  = 8;
constexpr int ZSEGS   = 8;
constexpr int ZLEN    = 16;
constexpr int NBLK    = NB * STRIPS * ZSEGS;   // 1024
constexpr int THREADS = 256;
constexpr int NACC    = 6;               // cmin,cmax,max,sds,s1,s2
constexpr unsigned U01 = 0x3C23D70Au;    // bits of 0.01f
constexpr unsigned U05 = 0x3F000000u;    // bits of 0.5f
}

__device__ float        g_part[NBLK * NACC];
__device__ unsigned int g_ticket = 0;

__device__ __forceinline__ void ldg256(float v[8], const char* p) {
    asm("ld.global.v8.f32 {%0,%1,%2,%3,%4,%5,%6,%7}, [%8];"
        : "=f"(v[0]), "=f"(v[1]), "=f"(v[2]), "=f"(v[3]),
          "=f"(v[4]), "=f"(v[5]), "=f"(v[6]), "=f"(v[7])
        : "l"(p));
}

struct St {
    unsigned cic;   // ci | (ch<<16)
    unsigned mxu;   // integer max (inputs non-negative)
    float sds, s1, s2;
};

__device__ __forceinline__ void body(const float v[8], const float prev[8],
                                     const char* pz,
                                     bool do_h, bool do_w, St& st) {
    const float nx = __shfl_down_sync(0xffffffffu, v[0], 1);
    float g = 0.f;
#pragma unroll
    for (int k = 1; k < 8; ++k) g += fabsf(v[k] - v[k - 1]);
    if (do_w) g += fabsf(nx - v[7]);

    // h row: just-in-time load; L1-hit (line v-prefetched 2 iters ago by
    // the row+1 threads of this block).
    if (do_h) {
        float h[8];
        ldg256(h, pz + 512);
#pragma unroll
        for (int k = 0; k < 8; ++k) g += fabsf(h[k] - v[k]);
    }
#pragma unroll
    for (int k = 0; k < 8; ++k) g += fabsf(v[k] - prev[k]);
    st.sds += g;

#pragma unroll
    for (int k = 0; k < 8; ++k) {
        const float    x  = v[k];
        const unsigned xu = __float_as_uint(x);
        if (xu > U01) {
            st.cic += 1u;
            st.s1  += x;
            st.s2   = fmaf(x, x, st.s2);
        }
        if (xu > U05) st.cic += 0x10000u;
        st.mxu = (xu > st.mxu) ? xu : st.mxu;
    }
}

__global__ __launch_bounds__(THREADS, 4)
void lesion_fused(const float* __restrict__ pred, float* __restrict__ out) {
    const int bid   = blockIdx.x;
    const int zseg  = bid & 7;
    const int strip = (bid >> 3) & 7;
    const int b     = bid >> 6;
    const int tid   = threadIdx.x;
    const int lane  = tid & 31;
    const int wid   = tid >> 5;

    const int col8 = tid & 15;             // 8-float column group (0..15)
    const int rloc = tid >> 4;             // row within strip (0..15)
    const int grow = strip * 16 + rloc;    // global row (0..127)
    const bool do_h = (grow < 127);
    const bool do_w = (col8 != 15);
    const int  z0   = zseg * ZLEN;

    const char* pv = reinterpret_cast<const char*>(pred) +
                     (size_t)b * 8388608 + (size_t)z0 * 65536 +
                     (size_t)grow * 512 + (size_t)col8 * 32;

    St st = {0u, 0u, 0.f, 0.f, 0.f};

    float V[4][8];
    // Seed: V[3] = prev plane (z0-1; z0==0 -> plane 0, self-diff = 0).
    ldg256(V[3], (z0 > 0) ? (pv - 65536) : pv);
    ldg256(V[0], pv);                       // plane 0
    ldg256(V[1], pv + 65536);               // plane 1

    for (int i0 = 0; i0 < ZLEN; i0 += 4) {
#pragma unroll
        for (int k = 0; k < 4; ++k) {
            const int i  = i0 + k;
            // distance-2 prefetch into the free ring slot (cur=k&3,
            // prev=(k+3)&3, inflight (k+1)&3 all distinct).
            const int zn = (i + 2 < ZLEN) ? (i + 2) : (ZLEN - 1);
            ldg256(V[(k + 2) & 3], pv + (size_t)zn * 65536);

            body(V[k & 3], V[(k + 3) & 3], pv + (size_t)i * 65536,
                 do_h, do_w, st);
        }
    }

    // ---- block reduction (8 warps) ----
    float acc[NACC] = {(float)(st.cic & 0xFFFFu), (float)(st.cic >> 16),
                       __uint_as_float(st.mxu), st.sds, st.s1, st.s2};
#pragma unroll
    for (int k = 0; k < NACC; ++k) {
#pragma unroll
        for (int off = 16; off; off >>= 1) {
            const float t = __shfl_xor_sync(0xffffffffu, acc[k], off);
            acc[k] = (k == 2) ? fmaxf(acc[k], t) : (acc[k] + t);
        }
    }
    __shared__ float red[8][NACC];
    __shared__ float fin[NB][NACC];
    __shared__ float lsh[NB];
    __shared__ unsigned int tick_sh;
    if (lane == 0) {
#pragma unroll
        for (int k = 0; k < NACC; ++k) red[wid][k] = acc[k];
    }
    __syncthreads();

    if (tid == 0) {
#pragma unroll
        for (int k = 0; k < NACC; ++k) {
            float r = red[0][k];
#pragma unroll
            for (int w = 1; w < 8; ++w)
                r = (k == 2) ? fmaxf(r, red[w][k]) : (r + red[w][k]);
            g_part[bid * NACC + k] = r;
        }
        __threadfence();
        tick_sh = atomicAdd(&g_ticket, 1u);
    }
    __syncthreads();
    if (tick_sh != (unsigned)(NBLK - 1)) return;

    // ---- last block: deterministic fixed-order final reduction ----
    __threadfence();  // acquire other blocks' g_part writes

    constexpr int PER_B = STRIPS * ZSEGS;  // 64 partials per batch
    if (tid < NB * NACC) {
        const int fb = tid / NACC;
        const int fk = tid % NACC;
        const float* base = &g_part[(fb * PER_B) * NACC + fk];
        float r = base[0];
#pragma unroll
        for (int c2 = 1; c2 < PER_B; ++c2) {
            const float t = base[c2 * NACC];
            r = (fk == 2) ? fmaxf(r, t) : (r + t);
        }
        fin[fb][fk] = r;
    }
    __syncthreads();

    if (tid < NB) {
        const float cnt   = fin[tid][0];
        const float chigh = fin[tid][1];
        const float mxv   = fin[tid][2];
        const float sg    = fin[tid][3];
        const float S1    = fin[tid][4];
        const float S2    = fin[tid][5];

        const float invN   = 1.f / 2097152.f;        // 1/128^3
        const float invND3 = 1.f / 6242304.f;        // 1/(3*127*128*128)

        const float act = cnt * invN;
        float loss = fmaxf(0.005f - act, 0.f) * 15.f;

        const float high = chigh * invN;
        loss += fmaxf(high - 0.03f, 0.f) * 5.f;

        const float avg_grad = sg * invND3;
        if (mxv > 0.3f) loss += fminf(avg_grad, 1.f) * 5.f;

        const float cnt_safe = fmaxf(cnt, 1.f);
        const float m  = S1 / cnt_safe;
        const float sq = fmaxf(S2 - 2.f * m * S1 + m * m * cnt, 0.f);
        const bool gate = (act > 0.001f) && (cnt > 1.f);
        const float var = gate ? (sq / fmaxf(cnt - 1.f, 1.f)) : 1.f;
        const float rel_std = sqrtf(var) / (m + 1e-6f);
        const float pen = expf(-5.f * rel_std);
        loss += (gate ? pen : 0.f) * 7.f;

        lsh[tid] = loss;
    }
    __syncthreads();
    if (tid == 0) {
        float t = 0.f;
#pragma unroll
        for (int i = 0; i < NB; ++i) t += lsh[i];
        out[0] = t * (1.f / 16.f);
        g_ticket = 0;  // reset for next (graph-replayed) launch
    }
}

extern "C" void kernel_launch(void* const* d_in, const int* in_sizes, int n_in,
                              void* d_out, int out_size) {
    (void)in_sizes; (void)n_in; (void)out_size;
    const float* pred = (const float*)d_in[0];
    float* out = (float*)d_out;
    lesion_fused<<<NBLK, THREADS>>>(pred, out);
}